// round 7
// baseline (speedup 1.0000x reference)
#include <cuda_runtime.h>
#include <cuda_bf16.h>
#include <cstdint>

typedef uint32_t u32;

#define NT     512
#define LMN    68
#define NTOT   77
#define XSTRB  176        // xT row bytes (80 n-cols padded)
#define ASTRB  272        // agg row bytes (128 d-cols padded)

// per-graph state block
#define XH_OF  0
#define XL_OF  22528
#define AH_OF  45056
#define AL_OF  66816
#define GSZ    88576
// shared misc
#define O_G    177152
#define O_BE   177664
#define O_SS   178176     // 2 x 80 floats
#define O_SW   178816
#define SMEM_SZ 179456

// frag tables: exact mma.m16n8k16 A-fragment layout, hi/lo split
__device__ uint4 g_af[5*5*2*32];        // adj  [band5][k5][hl2][lane32]
__device__ uint4 g_wf[4*8*8*2*32];      // W^T  [L4][band8][k8][hl2][lane32]

__constant__ int2 c_reg[9] = {
  {0,16},{17,21},{22,26},{27,30},{31,35},{36,41},{42,47},{48,59},{60,67}
};

__device__ __forceinline__ u32 cvt2bf(float a, float b){ // lo16=bf16(a), hi16=bf16(b)
  u32 r; asm("cvt.rn.bf16x2.f32 %0, %1, %2;" : "=r"(r) : "f"(b), "f"(a)); return r;
}
__device__ __forceinline__ u32 split_lo(float p, float q, u32 h){
  return cvt2bf(p - __uint_as_float(h<<16), q - __uint_as_float(h & 0xFFFF0000u));
}
__device__ __forceinline__ void ldm4(u32* r, u32 addr){
  asm volatile("ldmatrix.sync.aligned.m8n8.x4.shared.b16 {%0,%1,%2,%3}, [%4];"
    : "=r"(r[0]),"=r"(r[1]),"=r"(r[2]),"=r"(r[3]) : "r"(addr));
}
__device__ __forceinline__ void mma(float* c, const u32* a, u32 b0, u32 b1){
  asm volatile("mma.sync.aligned.m16n8k16.row.col.f32.bf16.bf16.f32 "
    "{%0,%1,%2,%3},{%4,%5,%6,%7},{%8,%9},{%0,%1,%2,%3};"
    : "+f"(c[0]),"+f"(c[1]),"+f"(c[2]),"+f"(c[3])
    : "r"(a[0]),"r"(a[1]),"r"(a[2]),"r"(a[3]), "r"(b0),"r"(b1));
}
#define GRPBAR() asm volatile("bar.sync %0, 256;" :: "r"(gid+1) : "memory")

// ---------------- GEMM1 body: warp computes NB n-bands x 32 d-cols, K=80 ----------------
template<int NB, int B0>
__device__ __forceinline__ void gemm1_body(float* acc, char* st, u32 xh_b, int nc,
                                           int lane, int rsel, int csel, int r0, int cc)
{
  #pragma unroll
  for (int q = 0; q < NB*16; q++) acc[q] = 0.f;
  #pragma unroll
  for (int k = 0; k < 5; k++){
    const int kc = k*16 + csel;
    u32 bh0[4], bh1[4], bl0[4], bl1[4];
    u32 ra0 = xh_b + (u32)((nc      + rsel)*XSTRB + kc*2);
    u32 ra1 = xh_b + (u32)((nc + 16 + rsel)*XSTRB + kc*2);
    ldm4(bh0, ra0); ldm4(bh1, ra1);
    ldm4(bl0, ra0 + (XL_OF - XH_OF)); ldm4(bl1, ra1 + (XL_OF - XH_OF));
    #pragma unroll
    for (int j = 0; j < NB; j++){
      const uint4* af = g_af + (((B0+j)*5 + k)*2)*32 + lane;
      uint4 aH = af[0], aL = af[32];
      float* c = acc + j*16;
      #pragma unroll
      for (int sn = 0; sn < 4; sn++){
        const u32* bhx = (sn < 2) ? bh0 : bh1;
        const u32* blx = (sn < 2) ? bl0 : bl1;
        const int u = sn & 1;
        mma(c+sn*4, (const u32*)&aH, bhx[u], bhx[2+u]);
        mma(c+sn*4, (const u32*)&aL, bhx[u], bhx[2+u]);
        mma(c+sn*4, (const u32*)&aH, blx[u], blx[2+u]);
      }
    }
  }
  // store -> agg hi/lo
  #pragma unroll
  for (int j = 0; j < NB; j++){
    const int band = B0 + j;
    #pragma unroll
    for (int sn = 0; sn < 4; sn++)
      #pragma unroll
      for (int h = 0; h < 2; h++){
        float pp = acc[j*16 + sn*4 + h*2], qq = acc[j*16 + sn*4 + h*2 + 1];
        u32 hi = cvt2bf(pp,qq);
        u32 lo = split_lo(pp,qq,hi);
        u32 off = (u32)((band*16 + r0 + h*8)*ASTRB + (nc + sn*8 + cc)*2);
        *(u32*)(st + AH_OF + off) = hi;
        *(u32*)(st + AL_OF + off) = lo;
      }
  }
}

// ---------------- GEMM2 MMA: warp computes 32 o-rows x NB n-bands, K=128 ----------------
template<int NB, int B0>
__device__ __forceinline__ void gemm2_mma(float* acc, u32 ah_b, int L, int ob,
                                          int lane, int rsel, int csel)
{
  #pragma unroll
  for (int q = 0; q < NB*16; q++) acc[q] = 0.f;
  #pragma unroll
  for (int k = 0; k < 8; k++){
    const int kc = k*16 + csel;
    u32 bh[NB][4], bl[NB][4];
    #pragma unroll
    for (int j = 0; j < NB; j++){
      u32 rb = ah_b + (u32)(((B0+j)*16 + rsel)*ASTRB + kc*2);
      ldm4(bh[j], rb);
      ldm4(bl[j], rb + (AL_OF - AH_OF));
    }
    #pragma unroll
    for (int sb = 0; sb < 2; sb++){
      const uint4* wf = g_wf + (((L*8 + ob*2 + sb)*8 + k)*2)*32 + lane;
      uint4 aH = wf[0], aL = wf[32];
      #pragma unroll
      for (int j = 0; j < NB; j++){
        float* c = acc + (sb*NB + j)*8;
        mma(c,   (const u32*)&aH, bh[j][0], bh[j][2]);
        mma(c,   (const u32*)&aL, bh[j][0], bh[j][2]);
        mma(c,   (const u32*)&aH, bl[j][0], bl[j][2]);
        mma(c+4, (const u32*)&aH, bh[j][1], bh[j][3]);
        mma(c+4, (const u32*)&aL, bh[j][1], bh[j][3]);
        mma(c+4, (const u32*)&aH, bl[j][1], bl[j][3]);
      }
    }
  }
}

// ---------------- GEMM2 epilogue ----------------
template<int NB, int B0>
__device__ __forceinline__ void gemm2_epi(const float* acc, char* st, float* xnat2,
                                          const float* bptr, int L, int mr,
                                          int lane, int r0, int cc)
{
  #pragma unroll
  for (int sb = 0; sb < 2; sb++){
    const float bias0 = __ldg(bptr + mr + sb*16 + r0);
    const float bias1 = __ldg(bptr + mr + sb*16 + r0 + 8);
    #pragma unroll
    for (int j = 0; j < NB; j++){
      const int ncb = (B0+j)*16;
      const float* c = acc + (sb*NB + j)*8;
      #pragma unroll
      for (int sn = 0; sn < 2; sn++)
        #pragma unroll
        for (int h = 0; h < 2; h++){
          const float bia = h ? bias1 : bias0;
          float f0 = fmaxf(c[sn*4 + h*2]     + bia, 0.f);
          float f1 = fmaxf(c[sn*4 + h*2 + 1] + bia, 0.f);
          const int row = mr + sb*16 + r0 + h*8;
          const int col = ncb + sn*8 + cc;
          if (L < 3){
            u32 off = (u32)(row*XSTRB + col*2);
            u32 hi = *(u32*)(st + XH_OF + off);
            u32 lo = *(u32*)(st + XL_OF + off);
            f0 += __uint_as_float(hi<<16)         + __uint_as_float(lo<<16);
            f1 += __uint_as_float(hi&0xFFFF0000u) + __uint_as_float(lo&0xFFFF0000u);
            u32 nh2 = cvt2bf(f0,f1);
            *(u32*)(st + XH_OF + off) = nh2;
            *(u32*)(st + XL_OF + off) = split_lo(f0,f1,nh2);
          } else {
            if (col   < NTOT) xnat2[col*132 + row]     = f0;
            if (col+1 < NTOT) xnat2[(col+1)*132 + row] = f1;
          }
        }
    }
  }
}

// ---------------- format kernel: build frag tables ----------------
__global__ void __launch_bounds__(256)
format_kernel(const float* __restrict__ adj,
              const float* __restrict__ W0, const float* __restrict__ W1,
              const float* __restrict__ W2, const float* __restrict__ W3)
{
  const int b = blockIdx.x;
  const float* Ws[4] = {W0,W1,W2,W3};
  if (b == 0){
    for (int idx = threadIdx.x; idx < 5*5*32; idx += 256){
      int lane = idx & 31, k = (idx >> 5) % 5, band = idx / 160;
      u32 H[4], L[4];
      #pragma unroll
      for (int j = 0; j < 4; j++){
        int row = band*16 + (lane>>2) + (j&1)*8;
        int cp  = k*16 + (lane&3)*2 + (j>>1)*8;
        float p = (row < NTOT && cp   < NTOT) ? adj[row*NTOT + cp]   : 0.f;
        float q = (row < NTOT && cp+1 < NTOT) ? adj[row*NTOT + cp+1] : 0.f;
        H[j] = cvt2bf(p,q);
        L[j] = split_lo(p,q,H[j]);
      }
      int base = ((band*5 + k)*2)*32 + lane;
      g_af[base]      = make_uint4(H[0],H[1],H[2],H[3]);
      g_af[base + 32] = make_uint4(L[0],L[1],L[2],L[3]);
    }
  } else {
    const float* W = Ws[b-1];
    for (int idx = threadIdx.x; idx < 8*8*32; idx += 256){
      int lane = idx & 31, k = (idx >> 5) & 7, band = idx >> 8;
      u32 H[4], L[4];
      #pragma unroll
      for (int j = 0; j < 4; j++){
        int row = band*16 + (lane>>2) + (j&1)*8;
        int cd  = k*16 + (lane&3)*2 + (j>>1)*8;
        float p = W[cd*128 + row];
        float q = W[(cd+1)*128 + row];
        H[j] = cvt2bf(p,q);
        L[j] = split_lo(p,q,H[j]);
      }
      int base = ((((b-1)*8 + band)*8 + k)*2)*32 + lane;
      g_wf[base]      = make_uint4(H[0],H[1],H[2],H[3]);
      g_wf[base + 32] = make_uint4(L[0],L[1],L[2],L[3]);
    }
  }
}

// ---------------- main kernel ----------------
__global__ void __launch_bounds__(NT, 1)
net_kernel(const float* __restrict__ lm,
           const float* __restrict__ Wr, const float* __restrict__ br,
           const float* __restrict__ b0, const float* __restrict__ b1,
           const float* __restrict__ b2, const float* __restrict__ b3,
           const float* __restrict__ gamma, const float* __restrict__ beta,
           float* __restrict__ out)
{
  extern __shared__ char sm8[];
  const int tid  = threadIdx.x;
  const int gid  = tid >> 8;            // group 0/1
  const int lt   = tid & 255;           // group-local tid
  const int wl   = lt >> 5;             // group-local warp 0..7
  const int lane = tid & 31;
  const int gg   = blockIdx.x*2 + gid;  // graph id

  char* st   = sm8 + gid*GSZ;           // this group's state block
  float* sG  = (float*)(sm8 + O_G);
  float* sBe = (float*)(sm8 + O_BE);
  float* sS  = (float*)(sm8 + O_SS) + gid*80;
  float* sSw = (float*)(sm8 + O_SW) + gid*80;
  float* xnat  = (float*)st;            // init fp32 scratch (aliases xT span)
  float* xnat2 = (float*)(st + AH_OF);  // final fp32 out (aliases agg span)

  const u32 sb   = (u32)__cvta_generic_to_shared(sm8);
  const u32 xh_b = sb + gid*GSZ + XH_OF;
  const u32 ah_b = sb + gid*GSZ + AH_OF;

  const int rsel = lane & 15;
  const int csel = (lane >> 4) << 3;
  const int r0   = lane >> 2;
  const int cc   = (lane & 3) * 2;

  const float* Bs[4] = {b0, b1, b2, b3};

  // ================= init (per group, independent) =================
  {
    const float4* src = (const float4*)(lm + (size_t)gg * (LMN*128));
    for (int i = lt; i < LMN*32; i += 256){
      int row = i >> 5, c4 = i & 31;
      ((float4*)(xnat + row*132))[c4] = src[i];
    }
  }
  if (tid < 128){ sG[tid] = gamma[tid]; sBe[tid] = beta[tid]; }
  GRPBAR();

  // region-pool scores
  {
    const float brv = __ldg(br);
    const float4 wv = __ldg((const float4*)Wr + lane);
    for (int n = wl; n < LMN; n += 8){
      float4 xv = ((const float4*)(xnat + n*132))[lane];
      float d = xv.x*wv.x + xv.y*wv.y + xv.z*wv.z + xv.w*wv.w;
      #pragma unroll
      for (int o = 16; o; o >>= 1) d += __shfl_xor_sync(0xffffffffu, d, o);
      if (lane == 0) sS[n] = d + brv;
    }
  }
  GRPBAR();
  if (lt < 9){
    int2 re = c_reg[lt];
    float mx = -3.4e38f;
    for (int n = re.x; n <= re.y; n++) mx = fmaxf(mx, sS[n]);
    float sum = 0.f;
    for (int n = re.x; n <= re.y; n++){ float e = expf(sS[n]-mx); sSw[n] = e; sum += e; }
    float inv = 1.f/sum;
    for (int n = re.x; n <= re.y; n++) sSw[n] *= inv;
  }
  GRPBAR();
  for (int i = lt; i < 9*128; i += 256){
    int r = i >> 7, d = i & 127;
    int2 re = c_reg[r];
    float acc = 0.f;
    for (int n = re.x; n <= re.y; n++) acc = fmaf(sSw[n], xnat[n*132 + d], acc);
    xnat[(LMN + r)*132 + d] = acc;
  }
  GRPBAR();

  // build initial xT[d=128][n<80] hi/lo (read-all-to-regs, then overwrite alias)
  {
    const int d  = lt >> 1;
    const int n0 = (lt & 1) * 40;
    float v[40];
    #pragma unroll
    for (int j = 0; j < 40; j++){
      int n = n0 + j;
      v[j] = (n < NTOT) ? xnat[n*132 + d] : 0.f;
    }
    GRPBAR();   // all reads done before writing over the alias
    #pragma unroll
    for (int c = 0; c < 5; c++){
      u32 H[4], L[4];
      #pragma unroll
      for (int p = 0; p < 4; p++){
        float a = v[c*8 + p*2], b = v[c*8 + p*2 + 1];
        H[p] = cvt2bf(a,b);
        L[p] = split_lo(a,b,H[p]);
      }
      u32 off = (u32)(d*XSTRB + (n0 + c*8)*2);
      *(uint4*)(st + XH_OF + off) = make_uint4(H[0],H[1],H[2],H[3]);
      *(uint4*)(st + XL_OF + off) = make_uint4(L[0],L[1],L[2],L[3]);
    }
  }
  __syncthreads();   // align both groups before phase loop

  // ================= anti-phased phase loop =================
  #pragma unroll 1
  for (int P = 0; P < 9; P++){
    int p = (gid == 0) ? P : P - 1;
    if (p >= 0 && p <= 7){
      int L = p >> 1;
      if (!(p & 1)){
        // ---------- GEMM1: agg[n<80][d<128] = adj @ x, K=80 ----------
        float acc[48];
        const int nc = (wl >> 1) * 32;
        if ((wl & 1) == 0) gemm1_body<3,0>(acc, st, xh_b, nc, lane, rsel, csel, r0, cc);
        else               gemm1_body<2,3>(acc, st, xh_b, nc, lane, rsel, csel, r0, cc);
      } else {
        // ---------- GEMM2: outT[o<128][n<80] = W^T @ agg^T, K=128 ----------
        float acc[48];
        const int ob = wl >> 1;
        const int mr = ob * 32;
        if ((wl & 1) == 0) gemm2_mma<3,0>(acc, ah_b, L, ob, lane, rsel, csel);
        else               gemm2_mma<2,3>(acc, ah_b, L, ob, lane, rsel, csel);
        if (L == 3) GRPBAR();   // all agg reads done before fp32 overwrite
        if ((wl & 1) == 0) gemm2_epi<3,0>(acc, st, xnat2, Bs[L], L, mr, lane, r0, cc);
        else               gemm2_epi<2,3>(acc, st, xnat2, Bs[L], L, mr, lane, r0, cc);
      }
    } else if (p == 8){
      // group0 LayerNorm + writeout (overlaps group1's last GEMM2)
      const float4 gv  = ((const float4*)sG)[lane];
      const float4 bev = ((const float4*)sBe)[lane];
      for (int n = wl; n < NTOT; n += 8){
        float4 v = *(const float4*)(xnat2 + n*132 + lane*4);
        float s  = v.x + v.y + v.z + v.w;
        float s2 = v.x*v.x + v.y*v.y + v.z*v.z + v.w*v.w;
        #pragma unroll
        for (int o = 16; o; o >>= 1){
          s  += __shfl_xor_sync(0xffffffffu, s,  o);
          s2 += __shfl_xor_sync(0xffffffffu, s2, o);
        }
        float mu  = s * (1.f/128.f);
        float var = s2 * (1.f/128.f) - mu*mu;
        float inv = rsqrtf(var + 1e-5f);
        float4 o4;
        o4.x = (v.x - mu)*inv*gv.x + bev.x;
        o4.y = (v.y - mu)*inv*gv.y + bev.y;
        o4.z = (v.z - mu)*inv*gv.z + bev.z;
        o4.w = (v.w - mu)*inv*gv.w + bev.w;
        ((float4*)(out + ((size_t)gg*NTOT + n)*128))[lane] = o4;
      }
    }
    __syncthreads();
  }

  // group1 LayerNorm + writeout
  __syncthreads();
  if (gid == 1){
    const float4 gv  = ((const float4*)sG)[lane];
    const float4 bev = ((const float4*)sBe)[lane];
    for (int n = wl; n < NTOT; n += 8){
      float4 v = *(const float4*)(xnat2 + n*132 + lane*4);
      float s  = v.x + v.y + v.z + v.w;
      float s2 = v.x*v.x + v.y*v.y + v.z*v.z + v.w*v.w;
      #pragma unroll
      for (int o = 16; o; o >>= 1){
        s  += __shfl_xor_sync(0xffffffffu, s,  o);
        s2 += __shfl_xor_sync(0xffffffffu, s2, o);
      }
      float mu  = s * (1.f/128.f);
      float var = s2 * (1.f/128.f) - mu*mu;
      float inv = rsqrtf(var + 1e-5f);
      float4 o4;
      o4.x = (v.x - mu)*inv*gv.x + bev.x;
      o4.y = (v.y - mu)*inv*gv.y + bev.y;
      o4.z = (v.z - mu)*inv*gv.z + bev.z;
      o4.w = (v.w - mu)*inv*gv.w + bev.w;
      ((float4*)(out + ((size_t)gg*NTOT + n)*128))[lane] = o4;
    }
  }
}

extern "C" void kernel_launch(void* const* d_in, const int* in_sizes, int n_in,
                              void* d_out, int out_size)
{
  const float* lm    = (const float*)d_in[0];
  const float* adj   = (const float*)d_in[1];
  const float* Wr    = (const float*)d_in[2];
  const float* br    = (const float*)d_in[3];
  const float* W0    = (const float*)d_in[4];
  const float* b0    = (const float*)d_in[5];
  const float* W1    = (const float*)d_in[6];
  const float* b1    = (const float*)d_in[7];
  const float* W2    = (const float*)d_in[8];
  const float* b2    = (const float*)d_in[9];
  const float* W3    = (const float*)d_in[10];
  const float* b3    = (const float*)d_in[11];
  const float* gamma = (const float*)d_in[12];
  const float* beta  = (const float*)d_in[13];
  float* out = (float*)d_out;

  format_kernel<<<5, 256>>>(adj, W0, W1, W2, W3);
  cudaFuncSetAttribute(net_kernel, cudaFuncAttributeMaxDynamicSharedMemorySize, SMEM_SZ);
  net_kernel<<<2048, NT, SMEM_SZ>>>(lm, Wr, br, b0, b1, b2, b3, gamma, beta, out);
}

// round 8
// speedup vs baseline: 1.5179x; 1.5179x over previous
#include <cuda_runtime.h>
#include <cuda_bf16.h>
#include <cstdint>

typedef uint32_t u32;

#define NT     256
#define LMN    68
#define NTOT   77
#define XSTRB  176        // xT row bytes (80 n-cols padded)
#define ASTRB  272        // agg row bytes (128 d-cols padded)

// state block (per CTA = one graph)
#define XH_OF  0
#define XL_OF  22528
#define AH_OF  45056
#define AL_OF  66816
#define GSZ    88576
#define O_G    (GSZ)
#define O_BE   (GSZ+512)
#define O_SS   (GSZ+1024)
#define O_SW   (GSZ+1408)
#define SMEM_SZ (GSZ+1792)   // 90368 B -> 2 CTAs/SM

// frag tables: exact mma.m16n8k16 A-fragment layout, hi/lo split
__device__ uint4 g_af[5*5*2*32];        // adj  [band5][k5][hl2][lane32]
__device__ uint4 g_wf[4*8*8*2*32];      // W^T  [L4][band8][k8][hl2][lane32]

__constant__ int2 c_reg[9] = {
  {0,16},{17,21},{22,26},{27,30},{31,35},{36,41},{42,47},{48,59},{60,67}
};

__device__ __forceinline__ u32 cvt2bf(float a, float b){ // lo16=bf16(a), hi16=bf16(b)
  u32 r; asm("cvt.rn.bf16x2.f32 %0, %1, %2;" : "=r"(r) : "f"(b), "f"(a)); return r;
}
__device__ __forceinline__ u32 split_lo(float p, float q, u32 h){
  return cvt2bf(p - __uint_as_float(h<<16), q - __uint_as_float(h & 0xFFFF0000u));
}
__device__ __forceinline__ void ldm4(u32* r, u32 addr){
  asm volatile("ldmatrix.sync.aligned.m8n8.x4.shared.b16 {%0,%1,%2,%3}, [%4];"
    : "=r"(r[0]),"=r"(r[1]),"=r"(r[2]),"=r"(r[3]) : "r"(addr));
}
__device__ __forceinline__ void mma(float* c, const u32* a, u32 b0, u32 b1){
  asm volatile("mma.sync.aligned.m16n8k16.row.col.f32.bf16.bf16.f32 "
    "{%0,%1,%2,%3},{%4,%5,%6,%7},{%8,%9},{%0,%1,%2,%3};"
    : "+f"(c[0]),"+f"(c[1]),"+f"(c[2]),"+f"(c[3])
    : "r"(a[0]),"r"(a[1]),"r"(a[2]),"r"(a[3]), "r"(b0),"r"(b1));
}

// ---------------- format kernel: build frag tables ----------------
__global__ void __launch_bounds__(256)
format_kernel(const float* __restrict__ adj,
              const float* __restrict__ W0, const float* __restrict__ W1,
              const float* __restrict__ W2, const float* __restrict__ W3)
{
  const int b = blockIdx.x;
  const float* Ws[4] = {W0,W1,W2,W3};
  if (b == 0){
    for (int idx = threadIdx.x; idx < 5*5*32; idx += 256){
      int lane = idx & 31, k = (idx >> 5) % 5, band = idx / 160;
      u32 H[4], L[4];
      #pragma unroll
      for (int j = 0; j < 4; j++){
        int row = band*16 + (lane>>2) + (j&1)*8;
        int cp  = k*16 + (lane&3)*2 + (j>>1)*8;
        float p = (row < NTOT && cp   < NTOT) ? adj[row*NTOT + cp]   : 0.f;
        float q = (row < NTOT && cp+1 < NTOT) ? adj[row*NTOT + cp+1] : 0.f;
        H[j] = cvt2bf(p,q);
        L[j] = split_lo(p,q,H[j]);
      }
      int base = ((band*5 + k)*2)*32 + lane;
      g_af[base]      = make_uint4(H[0],H[1],H[2],H[3]);
      g_af[base + 32] = make_uint4(L[0],L[1],L[2],L[3]);
    }
  } else {
    const float* W = Ws[b-1];
    for (int idx = threadIdx.x; idx < 8*8*32; idx += 256){
      int lane = idx & 31, k = (idx >> 5) & 7, band = idx >> 8;
      u32 H[4], L[4];
      #pragma unroll
      for (int j = 0; j < 4; j++){
        int row = band*16 + (lane>>2) + (j&1)*8;
        int cd  = k*16 + (lane&3)*2 + (j>>1)*8;
        float p = W[cd*128 + row];
        float q = W[(cd+1)*128 + row];
        H[j] = cvt2bf(p,q);
        L[j] = split_lo(p,q,H[j]);
      }
      int base = ((((b-1)*8 + band)*8 + k)*2)*32 + lane;
      g_wf[base]      = make_uint4(H[0],H[1],H[2],H[3]);
      g_wf[base + 32] = make_uint4(L[0],L[1],L[2],L[3]);
    }
  }
}

// ---------------- main kernel: one graph per 256-thread CTA, 2 CTAs/SM ----------------
__global__ void __launch_bounds__(NT, 2)
net_kernel(const float* __restrict__ lm,
           const float* __restrict__ Wr, const float* __restrict__ br,
           const float* __restrict__ b0, const float* __restrict__ b1,
           const float* __restrict__ b2, const float* __restrict__ b3,
           const float* __restrict__ gamma, const float* __restrict__ beta,
           float* __restrict__ out)
{
  extern __shared__ char st[];
  const int tid  = threadIdx.x;
  const int wl   = tid >> 5;            // warp 0..7
  const int lane = tid & 31;
  const int gg   = blockIdx.x;          // graph id

  float* sG  = (float*)(st + O_G);
  float* sBe = (float*)(st + O_BE);
  float* sS  = (float*)(st + O_SS);
  float* sSw = (float*)(st + O_SW);
  float* xnat  = (float*)st;            // init fp32 scratch (aliases xT span)
  float* xnat2 = (float*)(st + AH_OF);  // final fp32 out (aliases agg span)

  const u32 sb   = (u32)__cvta_generic_to_shared(st);
  const u32 xh_b = sb + XH_OF;
  const u32 ah_b = sb + AH_OF;

  const int rsel = lane & 15;
  const int csel = (lane >> 4) << 3;
  const int r0   = lane >> 2;
  const int cc   = (lane & 3) * 2;

  const float* Bs[4] = {b0, b1, b2, b3};

  // ================= init =================
  {
    const float4* src = (const float4*)(lm + (size_t)gg * (LMN*128));
    for (int i = tid; i < LMN*32; i += NT){
      int row = i >> 5, c4 = i & 31;
      ((float4*)(xnat + row*132))[c4] = src[i];
    }
  }
  if (tid < 128){ sG[tid] = gamma[tid]; sBe[tid] = beta[tid]; }
  __syncthreads();

  // region-pool scores
  {
    const float brv = __ldg(br);
    const float4 wv = __ldg((const float4*)Wr + lane);
    for (int n = wl; n < LMN; n += 8){
      float4 xv = ((const float4*)(xnat + n*132))[lane];
      float d = xv.x*wv.x + xv.y*wv.y + xv.z*wv.z + xv.w*wv.w;
      #pragma unroll
      for (int o = 16; o; o >>= 1) d += __shfl_xor_sync(0xffffffffu, d, o);
      if (lane == 0) sS[n] = d + brv;
    }
  }
  __syncthreads();
  if (tid < 9){
    int2 re = c_reg[tid];
    float mx = -3.4e38f;
    for (int n = re.x; n <= re.y; n++) mx = fmaxf(mx, sS[n]);
    float sum = 0.f;
    for (int n = re.x; n <= re.y; n++){ float e = expf(sS[n]-mx); sSw[n] = e; sum += e; }
    float inv = 1.f/sum;
    for (int n = re.x; n <= re.y; n++) sSw[n] *= inv;
  }
  __syncthreads();
  for (int i = tid; i < 9*128; i += NT){
    int r = i >> 7, d = i & 127;
    int2 re = c_reg[r];
    float acc = 0.f;
    for (int n = re.x; n <= re.y; n++) acc = fmaf(sSw[n], xnat[n*132 + d], acc);
    xnat[(LMN + r)*132 + d] = acc;
  }
  __syncthreads();

  // build initial xT[d=128][n<80] hi/lo (read-all-to-regs, then overwrite alias)
  {
    const int d  = tid >> 1;
    const int n0 = (tid & 1) * 40;
    float v[40];
    #pragma unroll
    for (int j = 0; j < 40; j++){
      int n = n0 + j;
      v[j] = (n < NTOT) ? xnat[n*132 + d] : 0.f;
    }
    __syncthreads();   // all reads done before writing over the alias
    #pragma unroll
    for (int c = 0; c < 5; c++){
      u32 H[4], L[4];
      #pragma unroll
      for (int p = 0; p < 4; p++){
        float a = v[c*8 + p*2], b = v[c*8 + p*2 + 1];
        H[p] = cvt2bf(a,b);
        L[p] = split_lo(a,b,H[p]);
      }
      u32 off = (u32)(d*XSTRB + (n0 + c*8)*2);
      *(uint4*)(st + XH_OF + off) = make_uint4(H[0],H[1],H[2],H[3]);
      *(uint4*)(st + XL_OF + off) = make_uint4(L[0],L[1],L[2],L[3]);
    }
  }
  __syncthreads();

  // ================= layer loop =================
  #pragma unroll 1
  for (int L = 0; L < 4; L++){
    // ---------- GEMM1: agg[n<80][d<128] = adj @ x, K=80 ----------
    {
      const int ntile = (wl < 4) ? 3 : 2;
      #pragma unroll 1
      for (int i = 0; i < ntile; i++){
        int t = wl + 8*i;
        int band = t % 5;              // n row-band (16)
        int nc   = (t / 5) * 32;       // d col-stripe (32)
        const uint4* af = g_af + ((band*5)*2)*32 + lane;
        float acc[16];
        #pragma unroll
        for (int q = 0; q < 16; q++) acc[q] = 0.f;
        uint4 aH = af[0], aL = af[32];
        #pragma unroll
        for (int k = 0; k < 5; k++){
          uint4 aH2, aL2;
          if (k < 4){ aH2 = af[(k+1)*64]; aL2 = af[(k+1)*64 + 32]; }
          const int kc = k*16 + csel;
          u32 bh0[4], bh1[4], bl0[4], bl1[4];
          {
            u32 ra0 = xh_b + (u32)((nc      + rsel)*XSTRB + kc*2);
            u32 ra1 = xh_b + (u32)((nc + 16 + rsel)*XSTRB + kc*2);
            ldm4(bh0, ra0); ldm4(bh1, ra1);
            ldm4(bl0, ra0 + (XL_OF - XH_OF)); ldm4(bl1, ra1 + (XL_OF - XH_OF));
          }
          #pragma unroll
          for (int sn = 0; sn < 4; sn++){
            float* c = acc + sn*4;
            const u32* bhx = (sn < 2) ? bh0 : bh1;
            const u32* blx = (sn < 2) ? bl0 : bl1;
            const int u = sn & 1;
            mma(c, (const u32*)&aH, bhx[u], bhx[2+u]);
            mma(c, (const u32*)&aL, bhx[u], bhx[2+u]);
            mma(c, (const u32*)&aH, blx[u], blx[2+u]);
          }
          aH = aH2; aL = aL2;
        }
        // store tile -> agg hi/lo
        #pragma unroll
        for (int sn = 0; sn < 4; sn++)
          #pragma unroll
          for (int h = 0; h < 2; h++){
            float pp = acc[sn*4 + h*2], qq = acc[sn*4 + h*2 + 1];
            u32 hi = cvt2bf(pp,qq);
            u32 lo = split_lo(pp,qq,hi);
            u32 off = (u32)((band*16 + r0 + h*8)*ASTRB + (nc + sn*8 + cc)*2);
            *(u32*)(st + AH_OF + off) = hi;
            *(u32*)(st + AL_OF + off) = lo;
          }
      }
    }
    __syncthreads();

    // ---------- GEMM2: outT[o<128][n<80] = W^T @ agg^T, K=128 ----------
    {
      const int mr = wl * 16;          // warp-private o row-band
      const float bias0 = __ldg(Bs[L] + mr + r0);
      const float bias1 = __ldg(Bs[L] + mr + r0 + 8);
      const uint4* wf = g_wf + (((L*8 + wl)*8)*2)*32 + lane;
      float acc[40];
      #pragma unroll
      for (int q = 0; q < 40; q++) acc[q] = 0.f;
      uint4 aH = wf[0], aL = wf[32];
      #pragma unroll
      for (int k = 0; k < 8; k++){
        uint4 aH2, aL2;
        if (k < 7){ aH2 = wf[(k+1)*64]; aL2 = wf[(k+1)*64 + 32]; }
        const int kc = k*16 + csel;
        #pragma unroll
        for (int i = 0; i < 5; i++){
          u32 bh[4], bl[4];
          u32 rb = ah_b + (u32)((i*16 + rsel)*ASTRB + kc*2);
          ldm4(bh, rb);
          ldm4(bl, rb + (AL_OF - AH_OF));
          float* c = acc + i*8;
          mma(c,   (const u32*)&aH, bh[0], bh[2]);
          mma(c,   (const u32*)&aL, bh[0], bh[2]);
          mma(c,   (const u32*)&aH, bl[0], bl[2]);
          mma(c+4, (const u32*)&aH, bh[1], bh[3]);
          mma(c+4, (const u32*)&aL, bh[1], bh[3]);
          mma(c+4, (const u32*)&aH, bl[1], bl[3]);
        }
        aH = aH2; aL = aL2;
      }
      // epilogue
      if (L == 3) __syncthreads();   // all agg reads done before fp32 overwrite
      #pragma unroll
      for (int i = 0; i < 5; i++){
        const int nc = i*16;
        #pragma unroll
        for (int sn = 0; sn < 2; sn++)
          #pragma unroll
          for (int h = 0; h < 2; h++){
            const float bia = h ? bias1 : bias0;
            float f0 = fmaxf(acc[i*8 + sn*4 + h*2]     + bia, 0.f);
            float f1 = fmaxf(acc[i*8 + sn*4 + h*2 + 1] + bia, 0.f);
            const int row = mr + r0 + h*8;
            const int col = nc + sn*8 + cc;
            if (L < 3){
              u32 off = (u32)(row*XSTRB + col*2);
              u32 hi = *(u32*)(st + XH_OF + off);
              u32 lo = *(u32*)(st + XL_OF + off);
              f0 += __uint_as_float(hi<<16)         + __uint_as_float(lo<<16);
              f1 += __uint_as_float(hi&0xFFFF0000u) + __uint_as_float(lo&0xFFFF0000u);
              u32 nh2 = cvt2bf(f0,f1);
              *(u32*)(st + XH_OF + off) = nh2;
              *(u32*)(st + XL_OF + off) = split_lo(f0,f1,nh2);
            } else {
              if (col   < NTOT) xnat2[col*132 + row]     = f0;
              if (col+1 < NTOT) xnat2[(col+1)*132 + row] = f1;
            }
          }
      }
    }
    __syncthreads();
  }

  // ================= LayerNorm + writeout =================
  {
    const float4 gv  = ((const float4*)sG)[lane];
    const float4 bev = ((const float4*)sBe)[lane];
    for (int n = wl; n < NTOT; n += 8){
      float4 v = *(const float4*)(xnat2 + n*132 + lane*4);
      float s  = v.x + v.y + v.z + v.w;
      float s2 = v.x*v.x + v.y*v.y + v.z*v.z + v.w*v.w;
      #pragma unroll
      for (int o = 16; o; o >>= 1){
        s  += __shfl_xor_sync(0xffffffffu, s,  o);
        s2 += __shfl_xor_sync(0xffffffffu, s2, o);
      }
      float mu  = s * (1.f/128.f);
      float var = s2 * (1.f/128.f) - mu*mu;
      float inv = rsqrtf(var + 1e-5f);
      float4 o4;
      o4.x = (v.x - mu)*inv*gv.x + bev.x;
      o4.y = (v.y - mu)*inv*gv.y + bev.y;
      o4.z = (v.z - mu)*inv*gv.z + bev.z;
      o4.w = (v.w - mu)*inv*gv.w + bev.w;
      ((float4*)(out + ((size_t)gg*NTOT + n)*128))[lane] = o4;
    }
  }
}

extern "C" void kernel_launch(void* const* d_in, const int* in_sizes, int n_in,
                              void* d_out, int out_size)
{
  const float* lm    = (const float*)d_in[0];
  const float* adj   = (const float*)d_in[1];
  const float* Wr    = (const float*)d_in[2];
  const float* br    = (const float*)d_in[3];
  const float* W0    = (const float*)d_in[4];
  const float* b0    = (const float*)d_in[5];
  const float* W1    = (const float*)d_in[6];
  const float* b1    = (const float*)d_in[7];
  const float* W2    = (const float*)d_in[8];
  const float* b2    = (const float*)d_in[9];
  const float* W3    = (const float*)d_in[10];
  const float* b3    = (const float*)d_in[11];
  const float* gamma = (const float*)d_in[12];
  const float* beta  = (const float*)d_in[13];
  float* out = (float*)d_out;

  format_kernel<<<5, 256>>>(adj, W0, W1, W2, W3);
  cudaFuncSetAttribute(net_kernel, cudaFuncAttributeMaxDynamicSharedMemorySize, SMEM_SZ);
  net_kernel<<<4096, NT, SMEM_SZ>>>(lm, Wr, br, b0, b1, b2, b3, gamma, beta, out);
}

// round 10
// speedup vs baseline: 1.5298x; 1.0079x over previous
#include <cuda_runtime.h>
#include <cuda_bf16.h>
#include <cstdint>

typedef uint32_t u32;

#define NT     256
#define LMN    68
#define NTOT   77
#define XSTRB  176        // xT row bytes (80 n-cols padded)
#define ASTRB  272        // agg row bytes (128 d-cols padded)

// state block (per CTA = one graph)
#define XH_OF  0
#define XL_OF  22528
#define AH_OF  45056
#define AL_OF  66816
#define GSZ    88576
#define O_G    (GSZ)
#define O_BE   (GSZ+512)
#define O_SS   (GSZ+1024)
#define O_SW   (GSZ+1408)
#define SMEM_SZ (GSZ+1792)   // 90368 B -> 2 CTAs/SM

// frag tables: exact mma.m16n8k16 A-fragment layout, hi/lo split
__device__ uint4 g_af[5*5*2*32];        // adj  [band5][k5][hl2][lane32]
__device__ uint4 g_wf[4*8*8*2*32];      // W^T  [L4][band8][k8][hl2][lane32]

__constant__ int2 c_reg[9] = {
  {0,16},{17,21},{22,26},{27,30},{31,35},{36,41},{42,47},{48,59},{60,67}
};

__device__ __forceinline__ u32 cvt2bf(float a, float b){ // lo16=bf16(a), hi16=bf16(b)
  u32 r; asm("cvt.rn.bf16x2.f32 %0, %1, %2;" : "=r"(r) : "f"(b), "f"(a)); return r;
}
__device__ __forceinline__ u32 split_lo(float p, float q, u32 h){
  return cvt2bf(p - __uint_as_float(h<<16), q - __uint_as_float(h & 0xFFFF0000u));
}
__device__ __forceinline__ void ldm4(u32* r, u32 addr){
  asm volatile("ldmatrix.sync.aligned.m8n8.x4.shared.b16 {%0,%1,%2,%3}, [%4];"
    : "=r"(r[0]),"=r"(r[1]),"=r"(r[2]),"=r"(r[3]) : "r"(addr));
}
__device__ __forceinline__ void mma(float* c, const u32* a, u32 b0, u32 b1){
  asm volatile("mma.sync.aligned.m16n8k16.row.col.f32.bf16.bf16.f32 "
    "{%0,%1,%2,%3},{%4,%5,%6,%7},{%8,%9},{%0,%1,%2,%3};"
    : "+f"(c[0]),"+f"(c[1]),"+f"(c[2]),"+f"(c[3])
    : "r"(a[0]),"r"(a[1]),"r"(a[2]),"r"(a[3]), "r"(b0),"r"(b1));
}

// ---------------- format kernel: build frag tables ----------------
__global__ void __launch_bounds__(256)
format_kernel(const float* __restrict__ adj,
              const float* __restrict__ W0, const float* __restrict__ W1,
              const float* __restrict__ W2, const float* __restrict__ W3)
{
  const int b = blockIdx.x;
  const float* Ws[4] = {W0,W1,W2,W3};
  if (b == 0){
    for (int idx = threadIdx.x; idx < 5*5*32; idx += 256){
      int lane = idx & 31, k = (idx >> 5) % 5, band = idx / 160;
      u32 H[4], L[4];
      #pragma unroll
      for (int j = 0; j < 4; j++){
        int row = band*16 + (lane>>2) + (j&1)*8;
        int cp  = k*16 + (lane&3)*2 + (j>>1)*8;
        float p = (row < NTOT && cp   < NTOT) ? adj[row*NTOT + cp]   : 0.f;
        float q = (row < NTOT && cp+1 < NTOT) ? adj[row*NTOT + cp+1] : 0.f;
        H[j] = cvt2bf(p,q);
        L[j] = split_lo(p,q,H[j]);
      }
      int base = ((band*5 + k)*2)*32 + lane;
      g_af[base]      = make_uint4(H[0],H[1],H[2],H[3]);
      g_af[base + 32] = make_uint4(L[0],L[1],L[2],L[3]);
    }
  } else {
    const float* W = Ws[b-1];
    for (int idx = threadIdx.x; idx < 8*8*32; idx += 256){
      int lane = idx & 31, k = (idx >> 5) & 7, band = idx >> 8;
      u32 H[4], L[4];
      #pragma unroll
      for (int j = 0; j < 4; j++){
        int row = band*16 + (lane>>2) + (j&1)*8;
        int cd  = k*16 + (lane&3)*2 + (j>>1)*8;
        float p = W[cd*128 + row];
        float q = W[(cd+1)*128 + row];
        H[j] = cvt2bf(p,q);
        L[j] = split_lo(p,q,H[j]);
      }
      int base = ((((b-1)*8 + band)*8 + k)*2)*32 + lane;
      g_wf[base]      = make_uint4(H[0],H[1],H[2],H[3]);
      g_wf[base + 32] = make_uint4(L[0],L[1],L[2],L[3]);
    }
  }
}

// ---------------- main kernel: one graph per 256-thread CTA, 2 CTAs/SM ----------------
__global__ void __launch_bounds__(NT, 2)
net_kernel(const float* __restrict__ lm,
           const float* __restrict__ Wr, const float* __restrict__ br,
           const float* __restrict__ b0, const float* __restrict__ b1,
           const float* __restrict__ b2, const float* __restrict__ b3,
           const float* __restrict__ gamma, const float* __restrict__ beta,
           float* __restrict__ out)
{
  extern __shared__ char st[];
  const int tid  = threadIdx.x;
  const int wl   = tid >> 5;            // warp 0..7
  const int lane = tid & 31;
  const int gg   = blockIdx.x;          // graph id

  float* sG  = (float*)(st + O_G);
  float* sBe = (float*)(st + O_BE);
  float* sS  = (float*)(st + O_SS);
  float* sSw = (float*)(st + O_SW);
  float* xnat  = (float*)st;            // init fp32 scratch (aliases xT span)
  float* xnat2 = (float*)(st + AH_OF);  // final fp32 out (aliases agg span)

  const u32 sb   = (u32)__cvta_generic_to_shared(st);
  const u32 xh_b = sb + XH_OF;
  const u32 ah_b = sb + AH_OF;

  const int rsel = lane & 15;
  const int csel = (lane >> 4) << 3;
  const int r0   = lane >> 2;
  const int cc   = (lane & 3) * 2;

  const float* Bs[4] = {b0, b1, b2, b3};

  // ================= init =================
  {
    const float4* src = (const float4*)(lm + (size_t)gg * (LMN*128));
    for (int i = tid; i < LMN*32; i += NT){
      int row = i >> 5, c4 = i & 31;
      ((float4*)(xnat + row*132))[c4] = src[i];
    }
  }
  if (tid < 128){ sG[tid] = gamma[tid]; sBe[tid] = beta[tid]; }
  __syncthreads();

  // region-pool scores
  {
    const float brv = __ldg(br);
    const float4 wv = __ldg((const float4*)Wr + lane);
    for (int n = wl; n < LMN; n += 8){
      float4 xv = ((const float4*)(xnat + n*132))[lane];
      float d = xv.x*wv.x + xv.y*wv.y + xv.z*wv.z + xv.w*wv.w;
      #pragma unroll
      for (int o = 16; o; o >>= 1) d += __shfl_xor_sync(0xffffffffu, d, o);
      if (lane == 0) sS[n] = d + brv;
    }
  }
  __syncthreads();
  if (tid < 9){
    int2 re = c_reg[tid];
    float mx = -3.4e38f;
    for (int n = re.x; n <= re.y; n++) mx = fmaxf(mx, sS[n]);
    float sum = 0.f;
    for (int n = re.x; n <= re.y; n++){ float e = expf(sS[n]-mx); sSw[n] = e; sum += e; }
    float inv = 1.f/sum;
    for (int n = re.x; n <= re.y; n++) sSw[n] *= inv;
  }
  __syncthreads();
  for (int i = tid; i < 9*128; i += NT){
    int r = i >> 7, d = i & 127;
    int2 re = c_reg[r];
    float acc = 0.f;
    for (int n = re.x; n <= re.y; n++) acc = fmaf(sSw[n], xnat[n*132 + d], acc);
    xnat[(LMN + r)*132 + d] = acc;
  }
  __syncthreads();

  // build initial xT[d=128][n<80] hi/lo (read-all-to-regs, then overwrite alias)
  {
    const int d  = tid >> 1;
    const int n0 = (tid & 1) * 40;
    float v[40];
    #pragma unroll
    for (int j = 0; j < 40; j++){
      int n = n0 + j;
      v[j] = (n < NTOT) ? xnat[n*132 + d] : 0.f;
    }
    __syncthreads();   // all reads done before writing over the alias
    #pragma unroll
    for (int c = 0; c < 5; c++){
      u32 H[4], L[4];
      #pragma unroll
      for (int p = 0; p < 4; p++){
        float a = v[c*8 + p*2], b = v[c*8 + p*2 + 1];
        H[p] = cvt2bf(a,b);
        L[p] = split_lo(a,b,H[p]);
      }
      u32 off = (u32)(d*XSTRB + (n0 + c*8)*2);
      *(uint4*)(st + XH_OF + off) = make_uint4(H[0],H[1],H[2],H[3]);
      *(uint4*)(st + XL_OF + off) = make_uint4(L[0],L[1],L[2],L[3]);
    }
  }
  __syncthreads();

  // ================= layer loop =================
  #pragma unroll 1
  for (int L = 0; L < 4; L++){
    // ---------- GEMM1: agg[n<80][d] = adj @ x ; warp tile 80n x 16d, K=80 ----------
    {
      const int nc = wl * 16;          // warp-private d-stripe
      float acc[40];
      #pragma unroll
      for (int q = 0; q < 40; q++) acc[q] = 0.f;
      #pragma unroll
      for (int k = 0; k < 5; k++){
        const int kc = k*16 + csel;
        u32 bh[4], bl[4];
        u32 ra = xh_b + (u32)((nc + rsel)*XSTRB + kc*2);
        ldm4(bh, ra);
        ldm4(bl, ra + (XL_OF - XH_OF));
        #pragma unroll
        for (int b = 0; b < 5; b++){
          uint4 aH = g_af[((b*5 + k)*2    )*32 + lane];
          uint4 aL = g_af[((b*5 + k)*2 + 1)*32 + lane];
          #pragma unroll
          for (int j = 0; j < 2; j++){
            float* c = acc + (b*2 + j)*4;
            mma(c, (const u32*)&aH, bh[j], bh[2+j]);
            mma(c, (const u32*)&aL, bh[j], bh[2+j]);
            mma(c, (const u32*)&aH, bl[j], bl[2+j]);
          }
        }
      }
      __syncthreads();                 // xT reads complete before any epilogue later overwrites
      // store -> agg hi/lo (disjoint region)
      #pragma unroll
      for (int b = 0; b < 5; b++)
        #pragma unroll
        for (int j = 0; j < 2; j++)
          #pragma unroll
          for (int h = 0; h < 2; h++){
            float pp = acc[(b*2+j)*4 + h*2], qq = acc[(b*2+j)*4 + h*2 + 1];
            u32 hi = cvt2bf(pp,qq);
            u32 lo = split_lo(pp,qq,hi);
            u32 off = (u32)((b*16 + r0 + h*8)*ASTRB + (nc + j*8 + cc)*2);
            *(u32*)(st + AH_OF + off) = hi;
            *(u32*)(st + AL_OF + off) = lo;
          }
    }
    __syncthreads();

    // ---------- GEMM2: outT[o][n] = W^T @ agg^T ; warp tile 32o x 40n, K=128 ----------
    {
      const int mr = (wl >> 1) * 32;   // o-stripe
      const int nb = (wl & 1) * 40;    // n-half
      const int band0 = (wl >> 1) * 2;
      const uint4* wf0 = g_wf + (((L*8 + band0    )*8)*2)*32 + lane;
      const uint4* wf1 = g_wf + (((L*8 + band0 + 1)*8)*2)*32 + lane;
      float acc[40];
      #pragma unroll
      for (int q = 0; q < 40; q++) acc[q] = 0.f;
      uint4 aH0 = wf0[0], aL0 = wf0[32];
      uint4 aH1 = wf1[0], aL1 = wf1[32];
      #pragma unroll
      for (int k = 0; k < 8; k++){
        uint4 nH0, nL0, nH1, nL1;
        if (k < 7){
          nH0 = wf0[(k+1)*64]; nL0 = wf0[(k+1)*64 + 32];
          nH1 = wf1[(k+1)*64]; nL1 = wf1[(k+1)*64 + 32];
        }
        const int kc = k*16 + csel;
        u32 bh01[4], bh23[4], bh4[4], bl01[4], bl23[4], bl4[4];
        {
          u32 rb = ah_b + (u32)((nb + rsel)*ASTRB + kc*2);
          ldm4(bh01, rb); ldm4(bl01, rb + (AL_OF - AH_OF));
          rb += 16*ASTRB;
          ldm4(bh23, rb); ldm4(bl23, rb + (AL_OF - AH_OF));
          // last band has only 8 valid rows (nb+32..nb+39). Clamp row-select to
          // &7 so ALL four 8x8 sub-matrices read in-bounds rows; matrices 1/3
          // become duplicates and are unused (bh4[1], bh4[3]).
          u32 rb4 = ah_b + (u32)((nb + 32 + (rsel & 7))*ASTRB + kc*2);
          ldm4(bh4, rb4); ldm4(bl4, rb4 + (AL_OF - AH_OF));
        }
        u32 B0h[5] = {bh01[0], bh01[1], bh23[0], bh23[1], bh4[0]};
        u32 B1h[5] = {bh01[2], bh01[3], bh23[2], bh23[3], bh4[2]};
        u32 B0l[5] = {bl01[0], bl01[1], bl23[0], bl23[1], bl4[0]};
        u32 B1l[5] = {bl01[2], bl01[3], bl23[2], bl23[3], bl4[2]};
        #pragma unroll
        for (int sb2 = 0; sb2 < 2; sb2++){
          const uint4* pH = sb2 ? &aH1 : &aH0;
          const uint4* pL = sb2 ? &aL1 : &aL0;
          #pragma unroll
          for (int j = 0; j < 5; j++){
            float* c = acc + (sb2*5 + j)*4;
            mma(c, (const u32*)pH, B0h[j], B1h[j]);
            mma(c, (const u32*)pL, B0h[j], B1h[j]);
            mma(c, (const u32*)pH, B0l[j], B1l[j]);
          }
        }
        aH0 = nH0; aL0 = nL0; aH1 = nH1; aL1 = nL1;
      }
      // epilogue
      if (L == 3) __syncthreads();   // all agg reads done before fp32 overwrite
      #pragma unroll
      for (int sb2 = 0; sb2 < 2; sb2++){
        const float bias0 = __ldg(Bs[L] + mr + sb2*16 + r0);
        const float bias1 = __ldg(Bs[L] + mr + sb2*16 + r0 + 8);
        #pragma unroll
        for (int j = 0; j < 5; j++){
          const float* c = acc + (sb2*5 + j)*4;
          #pragma unroll
          for (int h = 0; h < 2; h++){
            const float bia = h ? bias1 : bias0;
            float f0 = fmaxf(c[h*2]     + bia, 0.f);
            float f1 = fmaxf(c[h*2 + 1] + bia, 0.f);
            const int row = mr + sb2*16 + r0 + h*8;
            const int col = nb + j*8 + cc;
            if (L < 3){
              u32 off = (u32)(row*XSTRB + col*2);
              u32 hi = *(u32*)(st + XH_OF + off);
              u32 lo = *(u32*)(st + XL_OF + off);
              f0 += __uint_as_float(hi<<16)         + __uint_as_float(lo<<16);
              f1 += __uint_as_float(hi&0xFFFF0000u) + __uint_as_float(lo&0xFFFF0000u);
              u32 nh2 = cvt2bf(f0,f1);
              *(u32*)(st + XH_OF + off) = nh2;
              *(u32*)(st + XL_OF + off) = split_lo(f0,f1,nh2);
            } else {
              if (col   < NTOT) xnat2[col*132 + row]     = f0;
              if (col+1 < NTOT) xnat2[(col+1)*132 + row] = f1;
            }
          }
        }
      }
    }
    __syncthreads();
  }

  // ================= LayerNorm + writeout =================
  {
    const float4 gv  = ((const float4*)sG)[lane];
    const float4 bev = ((const float4*)sBe)[lane];
    for (int n = wl; n < NTOT; n += 8){
      float4 v = *(const float4*)(xnat2 + n*132 + lane*4);
      float s  = v.x + v.y + v.z + v.w;
      float s2 = v.x*v.x + v.y*v.y + v.z*v.z + v.w*v.w;
      #pragma unroll
      for (int o = 16; o; o >>= 1){
        s  += __shfl_xor_sync(0xffffffffu, s,  o);
        s2 += __shfl_xor_sync(0xffffffffu, s2, o);
      }
      float mu  = s * (1.f/128.f);
      float var = s2 * (1.f/128.f) - mu*mu;
      float inv = rsqrtf(var + 1e-5f);
      float4 o4;
      o4.x = (v.x - mu)*inv*gv.x + bev.x;
      o4.y = (v.y - mu)*inv*gv.y + bev.y;
      o4.z = (v.z - mu)*inv*gv.z + bev.z;
      o4.w = (v.w - mu)*inv*gv.w + bev.w;
      ((float4*)(out + ((size_t)gg*NTOT + n)*128))[lane] = o4;
    }
  }
}

extern "C" void kernel_launch(void* const* d_in, const int* in_sizes, int n_in,
                              void* d_out, int out_size)
{
  const float* lm    = (const float*)d_in[0];
  const float* adj   = (const float*)d_in[1];
  const float* Wr    = (const float*)d_in[2];
  const float* br    = (const float*)d_in[3];
  const float* W0    = (const float*)d_in[4];
  const float* b0    = (const float*)d_in[5];
  const float* W1    = (const float*)d_in[6];
  const float* b1    = (const float*)d_in[7];
  const float* W2    = (const float*)d_in[8];
  const float* b2    = (const float*)d_in[9];
  const float* W3    = (const float*)d_in[10];
  const float* b3    = (const float*)d_in[11];
  const float* gamma = (const float*)d_in[12];
  const float* beta  = (const float*)d_in[13];
  float* out = (float*)d_out;

  format_kernel<<<5, 256>>>(adj, W0, W1, W2, W3);
  cudaFuncSetAttribute(net_kernel, cudaFuncAttributeMaxDynamicSharedMemorySize, SMEM_SZ);
  net_kernel<<<4096, NT, SMEM_SZ>>>(lm, Wr, br, b0, b1, b2, b3, gamma, beta, out);
}